// round 1
// baseline (speedup 1.0000x reference)
#include <cuda_runtime.h>

// ---------------- constants ----------------
#define NPATCH 1024          // 64 tiles * B=16
#define NG     8192          // NPATCH * G

// ---------------- scratch (__device__ globals; no allocs allowed) ----------------
__device__ float g_xp [NPATCH * 256 * 64];   // normalized, patchified x  (67 MB)
__device__ float g_ao [NPATCH * 512 * 64];   // per-group attention output (134 MB)
__device__ float g_wot[512 * 256];           // wo transposed

// packed f32x2 fma (sm_103a)
static __device__ __forceinline__ float2 ffma2(float2 a, float2 b, float2 c) {
    union U { float2 f; unsigned long long u; };
    U A, Bv, C, D;
    A.f = a; Bv.f = b; C.f = c;
    asm("fma.rn.f32x2 %0, %1, %2, %3;" : "=l"(D.u) : "l"(A.u), "l"(Bv.u), "l"(C.u));
    return D.f;
}

// ---------------- K0: transpose wo (256,512) -> wot (512,256) ----------------
__global__ void k0_transpose_wo(const float* __restrict__ wo) {
    int idx = blockIdx.x * 256 + threadIdx.x;
    if (idx < 256 * 512) {
        int c  = idx >> 9;      // 0..255
        int c2 = idx & 511;     // 0..511
        g_wot[c2 * 256 + c] = wo[idx];
    }
}

// ---------------- K1: LayerNorm over C + patchify ----------------
// grid: 2048 blocks (b, h, half-of-row), 256 threads
__global__ void __launch_bounds__(256) k1_ln_patch(const float* __restrict__ x,
                                                   const float* __restrict__ ln_g,
                                                   const float* __restrict__ ln_b) {
    __shared__ float sb[256 * 32];     // [c][w_local]
    __shared__ float rs[8 * 32], rq2[8 * 32];
    __shared__ float smu[32], srd[32];

    int bid  = blockIdx.x;
    int b    = bid >> 7;
    int h    = (bid >> 1) & 63;
    int half = bid & 1;
    int w0   = half * 32;
    int tid  = threadIdx.x;
    int wl   = tid & 31;
    int cs   = tid >> 5;               // 0..7, each owns 32 channels

    float sum = 0.f, sq = 0.f;
    const float* xb = x + (((long)b * 256 + cs * 32) * 64 + h) * 64 + w0 + wl;
    #pragma unroll 8
    for (int m = 0; m < 32; m++) {
        float v = xb[m * 4096];        // channel stride = 64*64
        sb[(cs * 32 + m) * 32 + wl] = v;
        sum += v; sq += v * v;
    }
    rs[cs * 32 + wl] = sum;
    rq2[cs * 32 + wl] = sq;
    __syncthreads();
    if (tid < 32) {
        float S = 0.f, Q = 0.f;
        #pragma unroll
        for (int s = 0; s < 8; s++) { S += rs[s * 32 + tid]; Q += rq2[s * 32 + tid]; }
        float mu  = S * (1.f / 256.f);
        float var = Q * (1.f / 256.f) - mu * mu;
        smu[tid] = mu;
        srd[tid] = rsqrtf(var + 1e-6f);
    }
    __syncthreads();
    float mu = smu[wl], rd = srd[wl];
    int w  = w0 + wl;
    int it = h >> 3, p = h & 7, jt = w >> 3, q = w & 7;
    int n  = it * 128 + jt * 16 + b;   // ((it*8+jt)*16 + b)
    float* dst = g_xp + (long)n * 256 * 64 + p * 8 + q;
    #pragma unroll 8
    for (int m = 0; m < 32; m++) {
        int c = cs * 32 + m;
        float v = (sb[c * 32 + wl] - mu) * rd * __ldg(ln_g + c) + __ldg(ln_b + c);
        dst[c * 64] = v;
    }
}

// ---------------- K2: per-(n,g) deformable attention ----------------
// smem float offsets
#define SM_XG   0        // 2048
#define SM_Q    2048     // 64*65 = 4160 (padded)
#define SM_W    6208     // 4096 (wq -> later wk|wv)
#define SM_W2T  10304    // 64*68 = 4352
#define SM_GB   14656    // 256
#define SM_KV   14912    // 128
#define SM_KK   15040    // 256
#define SM_VV   15296    // 256
#define SM_LG   15552    // 256
#define SM_AT   15808    // 256
#define SM_SP   16064    // 16  (sx[4] sy[4] kpx[4] kpy[4])
#define SM_C1   16080    // 128
#define SM_B1   16208    // 64
#define SM_B2   16272    // 64
#define SM_C3   16336    // 64
#define SM_B3   16400    // 1
#define K2_SMEM_BYTES (16416 * 4)

__global__ void __launch_bounds__(256) k2_attn(
    const float* __restrict__ wq, const float* __restrict__ wk, const float* __restrict__ wv,
    const float* __restrict__ ow1, const float* __restrict__ ob1, const float* __restrict__ ow2,
    const float* __restrict__ cw1g, const float* __restrict__ cb1g,
    const float* __restrict__ cw2g, const float* __restrict__ cb2g,
    const float* __restrict__ cw3g, const float* __restrict__ cb3g) {
    extern __shared__ float sm[];
    float* s_xg  = sm + SM_XG;
    float* s_q   = sm + SM_Q;
    float* s_w   = sm + SM_W;
    float* s_w2t = sm + SM_W2T;
    float* s_gb  = sm + SM_GB;
    float* s_kv  = sm + SM_KV;
    float* s_kk  = sm + SM_KK;
    float* s_vv  = sm + SM_VV;
    float* s_lg  = sm + SM_LG;
    float* s_at  = sm + SM_AT;
    float* s_sp  = sm + SM_SP;
    float* s_c1  = sm + SM_C1;
    float* s_b1  = sm + SM_B1;
    float* s_b2  = sm + SM_B2;
    float* s_c3  = sm + SM_C3;
    float* s_b3  = sm + SM_B3;

    int tid = threadIdx.x;
    int ng  = blockIdx.x;
    int n   = ng >> 3, g = ng & 7;

    // ---- P0: loads ----
    {
        const float4* src = (const float4*)(g_xp + ((long)n * 256 + g * 32) * 64);
        float4* dx = (float4*)s_xg;
        for (int idx = tid; idx < 512; idx += 256) dx[idx] = src[idx];
        const float4* wqs = (const float4*)(wq + g * 2048);
        float4* dw = (float4*)s_w;
        for (int idx = tid; idx < 512; idx += 256) dw[idx] = wqs[idx];
        for (int idx = tid; idx < 4096; idx += 256) {
            int kkk = idx >> 6, o = idx & 63;
            s_w2t[o * 68 + kkk] = cw2g[idx];   // w2t[o][k] = w2[k][o]
        }
        if (tid < 128) s_c1[tid] = cw1g[tid];
        if (tid < 64) { s_b1[tid] = cb1g[tid]; s_b2[tid] = cb2g[tid]; s_c3[tid] = cw3g[tid]; }
        if (tid == 0) s_b3[0] = cb3g[0];
    }
    __syncthreads();

    // ---- P1: q projection  q[o][i] = sum_c wq[o][c] * xg[c][i] ----
    {
        int o = tid >> 2, ib = (tid & 3) * 16;
        float acc[16];
        #pragma unroll
        for (int r = 0; r < 16; r++) acc[r] = 0.f;
        const float* wr = s_w + o * 32;
        #pragma unroll 8
        for (int c = 0; c < 32; c++) {
            float wv_ = wr[c];
            const float* xr = s_xg + c * 64 + ib;
            #pragma unroll
            for (int r = 0; r < 16; r++) acc[r] = fmaf(wv_, xr[r], acc[r]);
        }
        float* qd = s_q + o * 65 + ib;
        #pragma unroll
        for (int r = 0; r < 16; r++) qd[r] = acc[r];
    }
    __syncthreads();

    // ---- P2: depthwise conv 6x6 stride 4 pad 1 + bias + exact GELU ----
    {
        int ch = tid >> 2, oo = tid & 3, oy = oo >> 1, ox = oo & 1;
        float acc = 0.f;
        const float* wc = ow1 + ch * 36;
        const float* qr = s_q + ch * 65;
        #pragma unroll
        for (int ky = 0; ky < 6; ky++) {
            int iy = oy * 4 - 1 + ky;
            if (iy < 0 || iy > 7) continue;
            #pragma unroll
            for (int kx = 0; kx < 6; kx++) {
                int ix = ox * 4 - 1 + kx;
                if (ix < 0 || ix > 7) continue;
                acc = fmaf(qr[iy * 8 + ix], __ldg(wc + ky * 6 + kx), acc);
            }
        }
        float vs = acc + __ldg(ob1 + ch);
        s_gb[ch * 4 + oo] = 0.5f * vs * (1.f + erff(vs * 0.70710678118654752f));
    }
    __syncthreads();

    // ---- P3: offsets (tid<4); concurrently load wk/wv (tid>=64) ----
    if (tid < 4) {
        int j = tid, row = j >> 1, col = j & 1;
        float ax = 0.f, ay = 0.f;
        for (int ch = 0; ch < 64; ch++) {
            float gv = s_gb[ch * 4 + j];
            ax = fmaf(__ldg(ow2 + ch), gv, ax);
            ay = fmaf(__ldg(ow2 + 64 + ch), gv, ay);
        }
        float vgx = (float)col + 4.f * tanhf(ax);
        float vgy = (float)row + 4.f * tanhf(ay);
        s_sp[j]      = 8.f * vgx - 0.5f;   // sample x (pixel space)
        s_sp[4 + j]  = 8.f * vgy - 0.5f;   // sample y
        s_sp[8 + j]  = 2.f * vgx - 1.f;    // normalized kpos x (for CPB)
        s_sp[12 + j] = 2.f * vgy - 1.f;    // normalized kpos y
    } else if (tid >= 64) {
        int t = tid - 64;
        const float4* ks = (const float4*)(wk + g * 2048);
        const float4* vs = (const float4*)(wv + g * 2048);
        float4* dw = (float4*)s_w;
        for (int idx = t; idx < 512; idx += 192) {
            dw[idx]       = ks[idx];
            dw[512 + idx] = vs[idx];
        }
    }
    __syncthreads();

    // ---- P4: bilinear sampling (zero padding) ----
    if (tid < 128) {
        int c = tid >> 2, j = tid & 3;
        float sx = s_sp[j], sy = s_sp[4 + j];
        float x0f = floorf(sx), y0f = floorf(sy);
        int x0 = (int)x0f, y0 = (int)y0f;
        float fx = sx - x0f, fy = sy - y0f;
        const float* xr = s_xg + c * 64;
        float acc = 0.f;
        if (y0 >= 0 && y0 < 8) {
            if (x0 >= 0 && x0 < 8)         acc = fmaf(xr[y0 * 8 + x0],       (1.f - fx) * (1.f - fy), acc);
            if (x0 + 1 >= 0 && x0 + 1 < 8) acc = fmaf(xr[y0 * 8 + x0 + 1],   fx * (1.f - fy),         acc);
        }
        if (y0 + 1 >= 0 && y0 + 1 < 8) {
            if (x0 >= 0 && x0 < 8)         acc = fmaf(xr[(y0 + 1) * 8 + x0],     (1.f - fx) * fy, acc);
            if (x0 + 1 >= 0 && x0 + 1 < 8) acc = fmaf(xr[(y0 + 1) * 8 + x0 + 1], fx * fy,         acc);
        }
        s_kv[c * 4 + j] = acc;
    }
    __syncthreads();

    // ---- P5: k, v projections ----
    {
        int o = tid >> 2, j = tid & 3;
        float ak = 0.f, av = 0.f;
        const float* wkr = s_w + o * 32;
        const float* wvr = s_w + 2048 + o * 32;
        #pragma unroll 8
        for (int c = 0; c < 32; c++) {
            float kvv = s_kv[c * 4 + j];
            ak = fmaf(wkr[c], kvv, ak);
            av = fmaf(wvr[c], kvv, av);
        }
        s_kk[o * 4 + j] = ak;
        s_vv[o * 4 + j] = av;
    }
    __syncthreads();

    // ---- P6+P7: sim + CPB MLP (per thread: one (i,j)) ----
    {
        int i = tid >> 2, j = tid & 3;
        float sim = 0.f;
        #pragma unroll 8
        for (int o = 0; o < 64; o++)
            sim = fmaf(s_q[o * 65 + i], s_kk[o * 4 + j], sim);
        sim *= 0.125f;  // DH^-0.5

        float qpx = (float)(i & 7) * (2.f / 7.f) - 1.f;
        float qpy = (float)(i >> 3) * (2.f / 7.f) - 1.f;
        float px = qpx - s_sp[8 + j];
        float py = qpy - s_sp[12 + j];
        float bx = copysignf(log1pf(fabsf(px)), px);
        float by = copysignf(log1pf(fabsf(py)), py);

        float2 h1[32];
        #pragma unroll
        for (int k2 = 0; k2 < 32; k2++) {
            float a0 = fmaf(bx, s_c1[2 * k2],     fmaf(by, s_c1[64 + 2 * k2],     s_b1[2 * k2]));
            float a1 = fmaf(bx, s_c1[2 * k2 + 1], fmaf(by, s_c1[64 + 2 * k2 + 1], s_b1[2 * k2 + 1]));
            h1[k2].x = fmaxf(a0, 0.f);
            h1[k2].y = fmaxf(a1, 0.f);
        }
        float outb = s_b3[0];
        #pragma unroll 2
        for (int o = 0; o < 64; o++) {
            float2 acc2; acc2.x = s_b2[o]; acc2.y = 0.f;
            const float4* wr = (const float4*)(s_w2t + o * 68);
            #pragma unroll
            for (int t4 = 0; t4 < 16; t4++) {
                float4 w4 = wr[t4];
                float2 wlo; wlo.x = w4.x; wlo.y = w4.y;
                float2 whi; whi.x = w4.z; whi.y = w4.w;
                acc2 = ffma2(h1[2 * t4],     wlo, acc2);
                acc2 = ffma2(h1[2 * t4 + 1], whi, acc2);
            }
            float h2 = acc2.x + acc2.y;
            outb = fmaf(s_c3[o], fmaxf(h2, 0.f), outb);
        }
        s_lg[tid] = sim + outb;
    }
    __syncthreads();

    // ---- P8: softmax over the 4 keys ----
    if (tid < 64) {
        float l0 = s_lg[tid * 4], l1 = s_lg[tid * 4 + 1], l2 = s_lg[tid * 4 + 2], l3 = s_lg[tid * 4 + 3];
        float m = fmaxf(fmaxf(l0, l1), fmaxf(l2, l3));
        float e0 = expf(l0 - m), e1 = expf(l1 - m), e2 = expf(l2 - m), e3 = expf(l3 - m);
        float inv = 1.f / (e0 + e1 + e2 + e3);
        s_at[tid * 4]     = e0 * inv;
        s_at[tid * 4 + 1] = e1 * inv;
        s_at[tid * 4 + 2] = e2 * inv;
        s_at[tid * 4 + 3] = e3 * inv;
    }
    __syncthreads();

    // ---- P9: out[d][i] = sum_j attn[i][j] * v[d][j] -> g_ao ----
    {
        int d = tid >> 2, ib = (tid & 3) * 16;
        float v0 = s_vv[d * 4], v1 = s_vv[d * 4 + 1], v2 = s_vv[d * 4 + 2], v3 = s_vv[d * 4 + 3];
        float* dst = g_ao + ((long)n * 512 + g * 64 + d) * 64 + ib;
        const float4* at = (const float4*)(s_at + ib * 4);
        #pragma unroll
        for (int r = 0; r < 16; r++) {
            float4 a = at[r];
            dst[r] = a.x * v0 + a.y * v1 + a.z * v2 + a.w * v3;
        }
    }
}

// ---------------- K3: output projection 512->256 + bias + un-patchify ----------------
__global__ void __launch_bounds__(256) k3_outproj(const float* __restrict__ bo,
                                                  float* __restrict__ out) {
    __shared__ float s_ao[4096];   // 64 c2-rows x 64 i
    int n = blockIdx.x, tid = threadIdx.x;
    int cq = tid >> 2, ih = tid & 3;
    int c0 = cq * 4, i0 = ih * 16;

    float2 acc[4][8];
    #pragma unroll
    for (int a = 0; a < 4; a++)
        #pragma unroll
        for (int p = 0; p < 8; p++) { acc[a][p].x = 0.f; acc[a][p].y = 0.f; }

    for (int cb = 0; cb < 8; cb++) {
        __syncthreads();
        const float4* src = (const float4*)(g_ao + ((long)n * 512 + cb * 64) * 64);
        float4* dstS = (float4*)s_ao;
        for (int idx = tid; idx < 1024; idx += 256) dstS[idx] = src[idx];
        __syncthreads();
        #pragma unroll 2
        for (int r = 0; r < 64; r++) {
            float4 w4 = __ldg((const float4*)(g_wot + (cb * 64 + r) * 256 + c0));
            const float4* av4 = (const float4*)(s_ao + r * 64 + i0);
            float4 A0 = av4[0], A1 = av4[1], A2 = av4[2], A3 = av4[3];
            float2 av[8];
            av[0].x = A0.x; av[0].y = A0.y;  av[1].x = A0.z; av[1].y = A0.w;
            av[2].x = A1.x; av[2].y = A1.y;  av[3].x = A1.z; av[3].y = A1.w;
            av[4].x = A2.x; av[4].y = A2.y;  av[5].x = A2.z; av[5].y = A2.w;
            av[6].x = A3.x; av[6].y = A3.y;  av[7].x = A3.z; av[7].y = A3.w;
            float2 ws[4];
            ws[0].x = ws[0].y = w4.x;  ws[1].x = ws[1].y = w4.y;
            ws[2].x = ws[2].y = w4.z;  ws[3].x = ws[3].y = w4.w;
            #pragma unroll
            for (int a = 0; a < 4; a++)
                #pragma unroll
                for (int p = 0; p < 8; p++)
                    acc[a][p] = ffma2(ws[a], av[p], acc[a][p]);
        }
    }

    int it = n >> 7, jt = (n >> 4) & 7, b = n & 15;
    #pragma unroll
    for (int a = 0; a < 4; a++) {
        int c = c0 + a;
        float bias = __ldg(bo + c);
        #pragma unroll
        for (int p = 0; p < 8; p++) {
            int i  = i0 + p * 2;
            int hh = it * 8 + (i >> 3);
            int ww = jt * 8 + (i & 7);
            float* dp = out + (((long)b * 256 + c) * 64 + hh) * 64 + ww;
            dp[0] = acc[a][p].x + bias;
            dp[1] = acc[a][p].y + bias;
        }
    }
}

// ---------------- launcher ----------------
extern "C" void kernel_launch(void* const* d_in, const int* in_sizes, int n_in,
                              void* d_out, int out_size) {
    (void)in_sizes; (void)n_in; (void)out_size;
    const float* x   = (const float*)d_in[0];
    const float* lng = (const float*)d_in[1];
    const float* lnb = (const float*)d_in[2];
    const float* wq  = (const float*)d_in[3];
    const float* wk  = (const float*)d_in[4];
    const float* wv  = (const float*)d_in[5];
    const float* ow1 = (const float*)d_in[6];
    const float* ob1 = (const float*)d_in[7];
    const float* ow2 = (const float*)d_in[8];
    const float* cw1 = (const float*)d_in[9];
    const float* cb1 = (const float*)d_in[10];
    const float* cw2 = (const float*)d_in[11];
    const float* cb2 = (const float*)d_in[12];
    const float* cw3 = (const float*)d_in[13];
    const float* cb3 = (const float*)d_in[14];
    const float* wo  = (const float*)d_in[15];
    const float* bo  = (const float*)d_in[16];
    float* out = (float*)d_out;

    k0_transpose_wo<<<512, 256>>>(wo);
    k1_ln_patch<<<2048, 256>>>(x, lng, lnb);
    cudaFuncSetAttribute(k2_attn, cudaFuncAttributeMaxDynamicSharedMemorySize, K2_SMEM_BYTES);
    k2_attn<<<NG, 256, K2_SMEM_BYTES>>>(wq, wk, wv, ow1, ob1, ow2,
                                        cw1, cb1, cw2, cb2, cw3, cb3);
    k3_outproj<<<NPATCH, 256>>>(bo, out);
}

// round 2
// speedup vs baseline: 1.3335x; 1.3335x over previous
#include <cuda_runtime.h>

// ---------------- constants ----------------
#define NPATCH 1024          // 64 tiles * B=16
#define NG     8192          // NPATCH * G

// ---------------- scratch (__device__ globals; no allocs allowed) ----------------
__device__ float g_xp [NPATCH * 256 * 64];   // normalized, patchified x
__device__ float g_ao [NPATCH * 512 * 64];   // per-group attention output
__device__ float g_wot[512 * 256];           // wo transposed

// packed f32x2 fma (sm_103a)
static __device__ __forceinline__ float2 ffma2(float2 a, float2 b, float2 c) {
    union U { float2 f; unsigned long long u; };
    U A, Bv, C, D;
    A.f = a; Bv.f = b; C.f = c;
    asm("fma.rn.f32x2 %0, %1, %2, %3;" : "=l"(D.u) : "l"(A.u), "l"(Bv.u), "l"(C.u));
    return D.f;
}

// ---------------- K0: transpose wo (256,512) -> wot (512,256) ----------------
__global__ void k0_transpose_wo(const float* __restrict__ wo) {
    int idx = blockIdx.x * 256 + threadIdx.x;
    if (idx < 256 * 512) {
        int c  = idx >> 9;      // 0..255
        int c2 = idx & 511;     // 0..511
        g_wot[c2 * 256 + c] = wo[idx];
    }
}

// ---------------- K1: LayerNorm over C + patchify ----------------
__global__ void __launch_bounds__(256) k1_ln_patch(const float* __restrict__ x,
                                                   const float* __restrict__ ln_g,
                                                   const float* __restrict__ ln_b) {
    __shared__ float sb[256 * 32];     // [c][w_local]
    __shared__ float rs[8 * 32], rq2[8 * 32];
    __shared__ float smu[32], srd[32];

    int bid  = blockIdx.x;
    int b    = bid >> 7;
    int h    = (bid >> 1) & 63;
    int half = bid & 1;
    int w0   = half * 32;
    int tid  = threadIdx.x;
    int wl   = tid & 31;
    int cs   = tid >> 5;               // 0..7, each owns 32 channels

    float sum = 0.f, sq = 0.f;
    const float* xb = x + (((long)b * 256 + cs * 32) * 64 + h) * 64 + w0 + wl;
    #pragma unroll 8
    for (int m = 0; m < 32; m++) {
        float v = xb[m * 4096];        // channel stride = 64*64
        sb[(cs * 32 + m) * 32 + wl] = v;
        sum += v; sq += v * v;
    }
    rs[cs * 32 + wl] = sum;
    rq2[cs * 32 + wl] = sq;
    __syncthreads();
    if (tid < 32) {
        float S = 0.f, Q = 0.f;
        #pragma unroll
        for (int s = 0; s < 8; s++) { S += rs[s * 32 + tid]; Q += rq2[s * 32 + tid]; }
        float mu  = S * (1.f / 256.f);
        float var = Q * (1.f / 256.f) - mu * mu;
        smu[tid] = mu;
        srd[tid] = rsqrtf(var + 1e-6f);
    }
    __syncthreads();
    float mu = smu[wl], rd = srd[wl];
    int w  = w0 + wl;
    int it = h >> 3, p = h & 7, jt = w >> 3, q = w & 7;
    int n  = it * 128 + jt * 16 + b;
    float* dst = g_xp + (long)n * 256 * 64 + p * 8 + q;
    #pragma unroll 8
    for (int m = 0; m < 32; m++) {
        int c = cs * 32 + m;
        float v = (sb[c * 32 + wl] - mu) * rd * __ldg(ln_g + c) + __ldg(ln_b + c);
        dst[c * 64] = v;
    }
}

// ---------------- K2: per-(n,g) deformable attention ----------------
#define SM_XG   0        // 2048
#define SM_Q    2048     // 64*65 = 4160 (padded)
#define SM_W    6208     // 4096 (wq -> later wk|wv)
#define SM_W2T  10304    // 64*68 = 4352
#define SM_GB   14656    // 256
#define SM_KV   14912    // 128
#define SM_KK   15040    // 256
#define SM_VV   15296    // 256
#define SM_LG   15552    // 256
#define SM_AT   15808    // 256
#define SM_SP   16064    // 16
#define SM_C1   16080    // 128
#define SM_B1   16208    // 64
#define SM_B2   16272    // 64
#define SM_C3   16336    // 64
#define SM_B3   16400    // 1
#define K2_SMEM_BYTES (16416 * 4)

__global__ void __launch_bounds__(256) k2_attn(
    const float* __restrict__ wq, const float* __restrict__ wk, const float* __restrict__ wv,
    const float* __restrict__ ow1, const float* __restrict__ ob1, const float* __restrict__ ow2,
    const float* __restrict__ cw1g, const float* __restrict__ cb1g,
    const float* __restrict__ cw2g, const float* __restrict__ cb2g,
    const float* __restrict__ cw3g, const float* __restrict__ cb3g) {
    extern __shared__ float sm[];
    float* s_xg  = sm + SM_XG;
    float* s_q   = sm + SM_Q;
    float* s_w   = sm + SM_W;
    float* s_w2t = sm + SM_W2T;
    float* s_gb  = sm + SM_GB;
    float* s_kv  = sm + SM_KV;
    float* s_kk  = sm + SM_KK;
    float* s_vv  = sm + SM_VV;
    float* s_lg  = sm + SM_LG;
    float* s_at  = sm + SM_AT;
    float* s_sp  = sm + SM_SP;
    float* s_c1  = sm + SM_C1;
    float* s_b1  = sm + SM_B1;
    float* s_b2  = sm + SM_B2;
    float* s_c3  = sm + SM_C3;
    float* s_b3  = sm + SM_B3;

    int tid = threadIdx.x;
    int ng  = blockIdx.x;
    int n   = ng >> 3, g = ng & 7;

    // ---- P0: loads ----
    {
        const float4* src = (const float4*)(g_xp + ((long)n * 256 + g * 32) * 64);
        float4* dx = (float4*)s_xg;
        for (int idx = tid; idx < 512; idx += 256) dx[idx] = src[idx];
        const float4* wqs = (const float4*)(wq + g * 2048);
        float4* dw = (float4*)s_w;
        for (int idx = tid; idx < 512; idx += 256) dw[idx] = wqs[idx];
        for (int idx = tid; idx < 4096; idx += 256) {
            int kkk = idx >> 6, o = idx & 63;
            s_w2t[o * 68 + kkk] = cw2g[idx];   // w2t[o][k] = w2[k][o]
        }
        if (tid < 128) s_c1[tid] = cw1g[tid];
        if (tid < 64) { s_b1[tid] = cb1g[tid]; s_b2[tid] = cb2g[tid]; s_c3[tid] = cw3g[tid]; }
        if (tid == 0) s_b3[0] = cb3g[0];
    }
    __syncthreads();

    // ---- P1: q projection ----
    {
        int o = tid >> 2, ib = (tid & 3) * 16;
        float acc[16];
        #pragma unroll
        for (int r = 0; r < 16; r++) acc[r] = 0.f;
        const float* wr = s_w + o * 32;
        #pragma unroll 8
        for (int c = 0; c < 32; c++) {
            float wv_ = wr[c];
            const float* xr = s_xg + c * 64 + ib;
            #pragma unroll
            for (int r = 0; r < 16; r++) acc[r] = fmaf(wv_, xr[r], acc[r]);
        }
        float* qd = s_q + o * 65 + ib;
        #pragma unroll
        for (int r = 0; r < 16; r++) qd[r] = acc[r];
    }
    __syncthreads();

    // ---- P2: depthwise conv 6x6 s4 p1 + bias + exact GELU ----
    {
        int ch = tid >> 2, oo = tid & 3, oy = oo >> 1, ox = oo & 1;
        float acc = 0.f;
        const float* wc = ow1 + ch * 36;
        const float* qr = s_q + ch * 65;
        #pragma unroll
        for (int ky = 0; ky < 6; ky++) {
            int iy = oy * 4 - 1 + ky;
            if (iy < 0 || iy > 7) continue;
            #pragma unroll
            for (int kx = 0; kx < 6; kx++) {
                int ix = ox * 4 - 1 + kx;
                if (ix < 0 || ix > 7) continue;
                acc = fmaf(qr[iy * 8 + ix], __ldg(wc + ky * 6 + kx), acc);
            }
        }
        float vs = acc + __ldg(ob1 + ch);
        s_gb[ch * 4 + oo] = 0.5f * vs * (1.f + erff(vs * 0.70710678118654752f));
    }
    __syncthreads();

    // ---- P3: offsets (tid<4); concurrently load wk/wv ----
    if (tid < 4) {
        int j = tid, row = j >> 1, col = j & 1;
        float ax = 0.f, ay = 0.f;
        for (int ch = 0; ch < 64; ch++) {
            float gv = s_gb[ch * 4 + j];
            ax = fmaf(__ldg(ow2 + ch), gv, ax);
            ay = fmaf(__ldg(ow2 + 64 + ch), gv, ay);
        }
        float vgx = (float)col + 4.f * tanhf(ax);
        float vgy = (float)row + 4.f * tanhf(ay);
        s_sp[j]      = 8.f * vgx - 0.5f;
        s_sp[4 + j]  = 8.f * vgy - 0.5f;
        s_sp[8 + j]  = 2.f * vgx - 1.f;
        s_sp[12 + j] = 2.f * vgy - 1.f;
    } else if (tid >= 64) {
        int t = tid - 64;
        const float4* ks = (const float4*)(wk + g * 2048);
        const float4* vs = (const float4*)(wv + g * 2048);
        float4* dw = (float4*)s_w;
        for (int idx = t; idx < 512; idx += 192) {
            dw[idx]       = ks[idx];
            dw[512 + idx] = vs[idx];
        }
    }
    __syncthreads();

    // ---- P4: bilinear sampling (zero padding) ----
    if (tid < 128) {
        int c = tid >> 2, j = tid & 3;
        float sx = s_sp[j], sy = s_sp[4 + j];
        float x0f = floorf(sx), y0f = floorf(sy);
        int x0 = (int)x0f, y0 = (int)y0f;
        float fx = sx - x0f, fy = sy - y0f;
        const float* xr = s_xg + c * 64;
        float acc = 0.f;
        if (y0 >= 0 && y0 < 8) {
            if (x0 >= 0 && x0 < 8)         acc = fmaf(xr[y0 * 8 + x0],       (1.f - fx) * (1.f - fy), acc);
            if (x0 + 1 >= 0 && x0 + 1 < 8) acc = fmaf(xr[y0 * 8 + x0 + 1],   fx * (1.f - fy),         acc);
        }
        if (y0 + 1 >= 0 && y0 + 1 < 8) {
            if (x0 >= 0 && x0 < 8)         acc = fmaf(xr[(y0 + 1) * 8 + x0],     (1.f - fx) * fy, acc);
            if (x0 + 1 >= 0 && x0 + 1 < 8) acc = fmaf(xr[(y0 + 1) * 8 + x0 + 1], fx * fy,         acc);
        }
        s_kv[c * 4 + j] = acc;
    }
    __syncthreads();

    // ---- P5: k, v projections ----
    {
        int o = tid >> 2, j = tid & 3;
        float ak = 0.f, av = 0.f;
        const float* wkr = s_w + o * 32;
        const float* wvr = s_w + 2048 + o * 32;
        #pragma unroll 8
        for (int c = 0; c < 32; c++) {
            float kvv = s_kv[c * 4 + j];
            ak = fmaf(wkr[c], kvv, ak);
            av = fmaf(wvr[c], kvv, av);
        }
        s_kk[o * 4 + j] = ak;
        s_vv[o * 4 + j] = av;
    }
    __syncthreads();

    // ---- P6+P7: sim + CPB MLP (4-way ILP) ----
    {
        int i = tid >> 2, j = tid & 3;
        float s0 = 0.f, s1 = 0.f, s2 = 0.f, s3 = 0.f;
        #pragma unroll
        for (int o = 0; o < 64; o += 4) {
            s0 = fmaf(s_q[(o + 0) * 65 + i], s_kk[(o + 0) * 4 + j], s0);
            s1 = fmaf(s_q[(o + 1) * 65 + i], s_kk[(o + 1) * 4 + j], s1);
            s2 = fmaf(s_q[(o + 2) * 65 + i], s_kk[(o + 2) * 4 + j], s2);
            s3 = fmaf(s_q[(o + 3) * 65 + i], s_kk[(o + 3) * 4 + j], s3);
        }
        float sim = ((s0 + s1) + (s2 + s3)) * 0.125f;

        float qpx = (float)(i & 7) * (2.f / 7.f) - 1.f;
        float qpy = (float)(i >> 3) * (2.f / 7.f) - 1.f;
        float px = qpx - s_sp[8 + j];
        float py = qpy - s_sp[12 + j];
        float bx = copysignf(log1pf(fabsf(px)), px);
        float by = copysignf(log1pf(fabsf(py)), py);

        float2 h1[32];
        #pragma unroll
        for (int k2 = 0; k2 < 32; k2++) {
            float a0 = fmaf(bx, s_c1[2 * k2],     fmaf(by, s_c1[64 + 2 * k2],     s_b1[2 * k2]));
            float a1 = fmaf(bx, s_c1[2 * k2 + 1], fmaf(by, s_c1[64 + 2 * k2 + 1], s_b1[2 * k2 + 1]));
            h1[k2].x = fmaxf(a0, 0.f);
            h1[k2].y = fmaxf(a1, 0.f);
        }
        float outb = s_b3[0];
        for (int ob = 0; ob < 64; ob += 4) {
            float2 a0, a1, a2, a3;
            a0.x = s_b2[ob + 0]; a0.y = 0.f;
            a1.x = s_b2[ob + 1]; a1.y = 0.f;
            a2.x = s_b2[ob + 2]; a2.y = 0.f;
            a3.x = s_b2[ob + 3]; a3.y = 0.f;
            const float4* w0p = (const float4*)(s_w2t + (ob + 0) * 68);
            const float4* w1p = (const float4*)(s_w2t + (ob + 1) * 68);
            const float4* w2p = (const float4*)(s_w2t + (ob + 2) * 68);
            const float4* w3p = (const float4*)(s_w2t + (ob + 3) * 68);
            #pragma unroll
            for (int t4 = 0; t4 < 16; t4++) {
                float2 hA = h1[2 * t4], hB = h1[2 * t4 + 1];
                float4 v0 = w0p[t4];
                float4 v1 = w1p[t4];
                float4 v2 = w2p[t4];
                float4 v3 = w3p[t4];
                float2 t;
                t.x = v0.x; t.y = v0.y; a0 = ffma2(hA, t, a0);
                t.x = v0.z; t.y = v0.w; a0 = ffma2(hB, t, a0);
                t.x = v1.x; t.y = v1.y; a1 = ffma2(hA, t, a1);
                t.x = v1.z; t.y = v1.w; a1 = ffma2(hB, t, a1);
                t.x = v2.x; t.y = v2.y; a2 = ffma2(hA, t, a2);
                t.x = v2.z; t.y = v2.w; a2 = ffma2(hB, t, a2);
                t.x = v3.x; t.y = v3.y; a3 = ffma2(hA, t, a3);
                t.x = v3.z; t.y = v3.w; a3 = ffma2(hB, t, a3);
            }
            outb = fmaf(s_c3[ob + 0], fmaxf(a0.x + a0.y, 0.f), outb);
            outb = fmaf(s_c3[ob + 1], fmaxf(a1.x + a1.y, 0.f), outb);
            outb = fmaf(s_c3[ob + 2], fmaxf(a2.x + a2.y, 0.f), outb);
            outb = fmaf(s_c3[ob + 3], fmaxf(a3.x + a3.y, 0.f), outb);
        }
        s_lg[tid] = sim + outb;
    }
    __syncthreads();

    // ---- P8: softmax over the 4 keys ----
    if (tid < 64) {
        float l0 = s_lg[tid * 4], l1 = s_lg[tid * 4 + 1], l2 = s_lg[tid * 4 + 2], l3 = s_lg[tid * 4 + 3];
        float m = fmaxf(fmaxf(l0, l1), fmaxf(l2, l3));
        float e0 = expf(l0 - m), e1 = expf(l1 - m), e2 = expf(l2 - m), e3 = expf(l3 - m);
        float inv = 1.f / (e0 + e1 + e2 + e3);
        s_at[tid * 4]     = e0 * inv;
        s_at[tid * 4 + 1] = e1 * inv;
        s_at[tid * 4 + 2] = e2 * inv;
        s_at[tid * 4 + 3] = e3 * inv;
    }
    __syncthreads();

    // ---- P9: out[d][i] = sum_j attn[i][j] * v[d][j] -> g_ao ----
    {
        int d = tid >> 2, ib = (tid & 3) * 16;
        float v0 = s_vv[d * 4], v1 = s_vv[d * 4 + 1], v2 = s_vv[d * 4 + 2], v3 = s_vv[d * 4 + 3];
        float* dst = g_ao + ((long)n * 512 + g * 64 + d) * 64 + ib;
        const float4* at = (const float4*)(s_at + ib * 4);
        #pragma unroll
        for (int r = 0; r < 16; r++) {
            float4 a = at[r];
            dst[r] = a.x * v0 + a.y * v1 + a.z * v2 + a.w * v3;
        }
    }
}

// ---------------- K3: output projection 512->256, smem-staged W + A ----------------
// dyn smem: s_w 64*256 floats (64KB) + s_a 64*64 floats (16KB) = 81920 B
#define K3_SMEM_BYTES ((64 * 256 + 64 * 64) * 4)
__global__ void __launch_bounds__(256, 2) k3_outproj(const float* __restrict__ bo,
                                                     float* __restrict__ out) {
    extern __shared__ float sm3[];
    float* s_w = sm3;                // [r][c]  64 x 256
    float* s_a = sm3 + 64 * 256;     // [r][i]  64 x 64

    int n = blockIdx.x, tid = threadIdx.x;
    int cg = tid >> 3, ig = tid & 7;
    int c0 = cg * 8, i0 = ig * 8;

    float2 acc[8][4];
    #pragma unroll
    for (int a = 0; a < 8; a++)
        #pragma unroll
        for (int p = 0; p < 4; p++) { acc[a][p].x = 0.f; acc[a][p].y = 0.f; }

    for (int cb = 0; cb < 8; cb++) {
        __syncthreads();
        {
            const float4* srcA = (const float4*)(g_ao + ((long)n * 512 + cb * 64) * 64);
            float4* dA = (float4*)s_a;
            #pragma unroll
            for (int t = 0; t < 4; t++) dA[tid + t * 256] = srcA[tid + t * 256];
            const float4* srcW = (const float4*)(g_wot + cb * 64 * 256);
            float4* dW = (float4*)s_w;
            #pragma unroll
            for (int t = 0; t < 16; t++) dW[tid + t * 256] = srcW[tid + t * 256];
        }
        __syncthreads();
        #pragma unroll 2
        for (int r = 0; r < 64; r++) {
            const float4* wp = (const float4*)(s_w + r * 256 + c0);
            float4 w0 = wp[0], w1 = wp[1];
            const float4* ap = (const float4*)(s_a + r * 64 + i0);
            float4 A0 = ap[0], A1 = ap[1];
            float2 av[4];
            av[0].x = A0.x; av[0].y = A0.y;
            av[1].x = A0.z; av[1].y = A0.w;
            av[2].x = A1.x; av[2].y = A1.y;
            av[3].x = A1.z; av[3].y = A1.w;
            float wc[8] = {w0.x, w0.y, w0.z, w0.w, w1.x, w1.y, w1.z, w1.w};
            #pragma unroll
            for (int a = 0; a < 8; a++) {
                float2 ws; ws.x = wc[a]; ws.y = wc[a];
                #pragma unroll
                for (int p = 0; p < 4; p++)
                    acc[a][p] = ffma2(ws, av[p], acc[a][p]);
            }
        }
    }

    int it = n >> 7, jt = (n >> 4) & 7, b = n & 15;
    int hh = it * 8 + ig;      // p = ig
    int ww = jt * 8;           // q = 0..7 contiguous
    #pragma unroll
    for (int a = 0; a < 8; a++) {
        int c = c0 + a;
        float bias = __ldg(bo + c);
        float4 o0, o1;
        o0.x = acc[a][0].x + bias; o0.y = acc[a][0].y + bias;
        o0.z = acc[a][1].x + bias; o0.w = acc[a][1].y + bias;
        o1.x = acc[a][2].x + bias; o1.y = acc[a][2].y + bias;
        o1.z = acc[a][3].x + bias; o1.w = acc[a][3].y + bias;
        float* dp = out + (((long)b * 256 + c) * 64 + hh) * 64 + ww;
        *(float4*)dp = o0;
        *(float4*)(dp + 4) = o1;
    }
}

// ---------------- launcher ----------------
extern "C" void kernel_launch(void* const* d_in, const int* in_sizes, int n_in,
                              void* d_out, int out_size) {
    (void)in_sizes; (void)n_in; (void)out_size;
    const float* x   = (const float*)d_in[0];
    const float* lng = (const float*)d_in[1];
    const float* lnb = (const float*)d_in[2];
    const float* wq  = (const float*)d_in[3];
    const float* wk  = (const float*)d_in[4];
    const float* wv  = (const float*)d_in[5];
    const float* ow1 = (const float*)d_in[6];
    const float* ob1 = (const float*)d_in[7];
    const float* ow2 = (const float*)d_in[8];
    const float* cw1 = (const float*)d_in[9];
    const float* cb1 = (const float*)d_in[10];
    const float* cw2 = (const float*)d_in[11];
    const float* cb2 = (const float*)d_in[12];
    const float* cw3 = (const float*)d_in[13];
    const float* cb3 = (const float*)d_in[14];
    const float* wo  = (const float*)d_in[15];
    const float* bo  = (const float*)d_in[16];
    float* out = (float*)d_out;

    k0_transpose_wo<<<512, 256>>>(wo);
    k1_ln_patch<<<2048, 256>>>(x, lng, lnb);
    cudaFuncSetAttribute(k2_attn, cudaFuncAttributeMaxDynamicSharedMemorySize, K2_SMEM_BYTES);
    k2_attn<<<NG, 256, K2_SMEM_BYTES>>>(wq, wk, wv, ow1, ob1, ow2,
                                        cw1, cb1, cw2, cb2, cw3, cb3);
    cudaFuncSetAttribute(k3_outproj, cudaFuncAttributeMaxDynamicSharedMemorySize, K3_SMEM_BYTES);
    k3_outproj<<<NPATCH, 256, K3_SMEM_BYTES>>>(bo, out);
}

// round 3
// speedup vs baseline: 2.1195x; 1.5894x over previous
#include <cuda_runtime.h>
#include <cuda_bf16.h>

// ---------------- constants ----------------
#define NPATCH 1024          // 64 tiles * B=16
#define NG     8192          // NPATCH * G

// ---------------- scratch ----------------
__device__ float g_xp[NPATCH * 256 * 64];    // normalized, patchified x  [n][c][i]
__device__ float g_ao[NPATCH * 64 * 512];    // attention output, TRANSPOSED [n][i][r]

// ---------------- mma helpers ----------------
static __device__ __forceinline__ void mma_bf16(float* d, const unsigned* a,
                                                unsigned b0, unsigned b1) {
    asm volatile("mma.sync.aligned.m16n8k16.row.col.f32.bf16.bf16.f32 "
        "{%0,%1,%2,%3},{%4,%5,%6,%7},{%8,%9},{%0,%1,%2,%3};"
        : "+f"(d[0]), "+f"(d[1]), "+f"(d[2]), "+f"(d[3])
        : "r"(a[0]), "r"(a[1]), "r"(a[2]), "r"(a[3]), "r"(b0), "r"(b1));
}
static __device__ __forceinline__ void mma_tf32(float* d, const unsigned* a,
                                                unsigned b0, unsigned b1) {
    asm volatile("mma.sync.aligned.m16n8k8.row.col.f32.tf32.tf32.f32 "
        "{%0,%1,%2,%3},{%4,%5,%6,%7},{%8,%9},{%0,%1,%2,%3};"
        : "+f"(d[0]), "+f"(d[1]), "+f"(d[2]), "+f"(d[3])
        : "r"(a[0]), "r"(a[1]), "r"(a[2]), "r"(a[3]), "r"(b0), "r"(b1));
}
static __device__ __forceinline__ float cvt_tf32(float x) {
    float r; asm("cvt.rna.tf32.f32 %0, %1;" : "=f"(r) : "f"(x)); return r;
}

// ---------------- K1: LayerNorm over C + patchify ----------------
__global__ void __launch_bounds__(256) k1_ln_patch(const float* __restrict__ x,
                                                   const float* __restrict__ ln_g,
                                                   const float* __restrict__ ln_b) {
    __shared__ float sb[256 * 32];
    __shared__ float rs[8 * 32], rq2[8 * 32];
    __shared__ float smu[32], srd[32];

    int bid  = blockIdx.x;
    int b    = bid >> 7;
    int h    = (bid >> 1) & 63;
    int half = bid & 1;
    int w0   = half * 32;
    int tid  = threadIdx.x;
    int wl   = tid & 31;
    int cs   = tid >> 5;

    float sum = 0.f, sq = 0.f;
    const float* xb = x + (((long)b * 256 + cs * 32) * 64 + h) * 64 + w0 + wl;
    #pragma unroll 8
    for (int m = 0; m < 32; m++) {
        float v = xb[m * 4096];
        sb[(cs * 32 + m) * 32 + wl] = v;
        sum += v; sq += v * v;
    }
    rs[cs * 32 + wl] = sum;
    rq2[cs * 32 + wl] = sq;
    __syncthreads();
    if (tid < 32) {
        float S = 0.f, Q = 0.f;
        #pragma unroll
        for (int s = 0; s < 8; s++) { S += rs[s * 32 + tid]; Q += rq2[s * 32 + tid]; }
        float mu  = S * (1.f / 256.f);
        float var = Q * (1.f / 256.f) - mu * mu;
        smu[tid] = mu;
        srd[tid] = rsqrtf(var + 1e-6f);
    }
    __syncthreads();
    float mu = smu[wl], rd = srd[wl];
    int w  = w0 + wl;
    int it = h >> 3, p = h & 7, jt = w >> 3, q = w & 7;
    int n  = it * 128 + jt * 16 + b;
    float* dst = g_xp + (long)n * 256 * 64 + p * 8 + q;
    #pragma unroll 8
    for (int m = 0; m < 32; m++) {
        int c = cs * 32 + m;
        float v = (sb[c * 32 + wl] - mu) * rd * __ldg(ln_g + c) + __ldg(ln_b + c);
        dst[c * 64] = v;
    }
}

// ---------------- K2: per-(n,g) deformable attention ----------------
// smem float offsets. [0,10304) = xg|w|q, later overlaid by bf16 h1 (256x68 bf16 = 8704 floats)
#define SM_XG   0        // 2048
#define SM_W    2048     // 4096 (wq, then wk|wv)
#define SM_Q    6144     // 64*65 = 4160
#define SM_W2B  10304    // 64x72 bf16 = 2304 floats
#define SM_GB   12608    // 256
#define SM_KV   12864    // 128
#define SM_KK   12992    // 256
#define SM_VV   13248    // 256
#define SM_LG   13504    // 256
#define SM_AT   13760    // 256
#define SM_SP   14016    // 16
#define SM_C1   14032    // 128
#define SM_B1   14160    // 64
#define SM_B2   14224    // 64
#define SM_C3   14288    // 64
#define SM_B3   14352    // 4
#define K2_SMEM_BYTES (14356 * 4)

__global__ void __launch_bounds__(256) k2_attn(
    const float* __restrict__ wq, const float* __restrict__ wk, const float* __restrict__ wv,
    const float* __restrict__ ow1, const float* __restrict__ ob1, const float* __restrict__ ow2,
    const float* __restrict__ cw1g, const float* __restrict__ cb1g,
    const float* __restrict__ cw2g, const float* __restrict__ cb2g,
    const float* __restrict__ cw3g, const float* __restrict__ cb3g) {
    extern __shared__ float sm[];
    float* s_xg  = sm + SM_XG;
    float* s_q   = sm + SM_Q;
    float* s_w   = sm + SM_W;
    float* s_gb  = sm + SM_GB;
    float* s_kv  = sm + SM_KV;
    float* s_kk  = sm + SM_KK;
    float* s_vv  = sm + SM_VV;
    float* s_lg  = sm + SM_LG;
    float* s_at  = sm + SM_AT;
    float* s_sp  = sm + SM_SP;
    float* s_c1  = sm + SM_C1;
    float* s_b1  = sm + SM_B1;
    float* s_b2  = sm + SM_B2;
    float* s_c3  = sm + SM_C3;
    float* s_b3  = sm + SM_B3;

    int tid = threadIdx.x;
    int ng  = blockIdx.x;
    int n   = ng >> 3, g = ng & 7;

    // ---- P0: loads ----
    {
        const float4* src = (const float4*)(g_xp + ((long)n * 256 + g * 32) * 64);
        float4* dx = (float4*)s_xg;
        for (int idx = tid; idx < 512; idx += 256) dx[idx] = src[idx];
        const float4* wqs = (const float4*)(wq + g * 2048);
        float4* dw = (float4*)s_w;
        for (int idx = tid; idx < 512; idx += 256) dw[idx] = wqs[idx];
        __nv_bfloat16* w2b = (__nv_bfloat16*)(sm + SM_W2B);
        for (int idx = tid; idx < 4096; idx += 256) {
            int k = idx >> 6, o = idx & 63;
            w2b[o * 72 + k] = __float2bfloat16(cw2g[idx]);   // w2b[o][k] = w2[k][o]
        }
        if (tid < 128) s_c1[tid] = cw1g[tid];
        if (tid < 64) { s_b1[tid] = cb1g[tid]; s_b2[tid] = cb2g[tid]; s_c3[tid] = cw3g[tid]; }
        if (tid == 0) s_b3[0] = cb3g[0];
    }
    __syncthreads();

    // ---- P1: q projection ----
    {
        int o = tid >> 2, ib = (tid & 3) * 16;
        float acc[16];
        #pragma unroll
        for (int r = 0; r < 16; r++) acc[r] = 0.f;
        const float* wr = s_w + o * 32;
        #pragma unroll 8
        for (int c = 0; c < 32; c++) {
            float wv_ = wr[c];
            const float* xr = s_xg + c * 64 + ib;
            #pragma unroll
            for (int r = 0; r < 16; r++) acc[r] = fmaf(wv_, xr[r], acc[r]);
        }
        float* qd = s_q + o * 65 + ib;
        #pragma unroll
        for (int r = 0; r < 16; r++) qd[r] = acc[r];
    }
    __syncthreads();

    // ---- P2: depthwise conv 6x6 s4 p1 + bias + exact GELU ----
    {
        int ch = tid >> 2, oo = tid & 3, oy = oo >> 1, ox = oo & 1;
        float acc = 0.f;
        const float* wc = ow1 + ch * 36;
        const float* qr = s_q + ch * 65;
        #pragma unroll
        for (int ky = 0; ky < 6; ky++) {
            int iy = oy * 4 - 1 + ky;
            if (iy < 0 || iy > 7) continue;
            #pragma unroll
            for (int kx = 0; kx < 6; kx++) {
                int ix = ox * 4 - 1 + kx;
                if (ix < 0 || ix > 7) continue;
                acc = fmaf(qr[iy * 8 + ix], __ldg(wc + ky * 6 + kx), acc);
            }
        }
        float vs = acc + __ldg(ob1 + ch);
        s_gb[ch * 4 + oo] = 0.5f * vs * (1.f + erff(vs * 0.70710678118654752f));
    }
    __syncthreads();

    // ---- P3: offsets (tid<4); concurrently load wk/wv ----
    if (tid < 4) {
        int j = tid, row = j >> 1, col = j & 1;
        float ax = 0.f, ay = 0.f;
        for (int ch = 0; ch < 64; ch++) {
            float gv = s_gb[ch * 4 + j];
            ax = fmaf(__ldg(ow2 + ch), gv, ax);
            ay = fmaf(__ldg(ow2 + 64 + ch), gv, ay);
        }
        float vgx = (float)col + 4.f * tanhf(ax);
        float vgy = (float)row + 4.f * tanhf(ay);
        s_sp[j]      = 8.f * vgx - 0.5f;
        s_sp[4 + j]  = 8.f * vgy - 0.5f;
        s_sp[8 + j]  = 2.f * vgx - 1.f;
        s_sp[12 + j] = 2.f * vgy - 1.f;
    } else if (tid >= 64) {
        int t = tid - 64;
        const float4* ks = (const float4*)(wk + g * 2048);
        const float4* vs = (const float4*)(wv + g * 2048);
        float4* dw = (float4*)s_w;
        for (int idx = t; idx < 512; idx += 192) {
            dw[idx]       = ks[idx];
            dw[512 + idx] = vs[idx];
        }
    }
    __syncthreads();

    // ---- P4: bilinear sampling (zero padding) ----
    if (tid < 128) {
        int c = tid >> 2, j = tid & 3;
        float sx = s_sp[j], sy = s_sp[4 + j];
        float x0f = floorf(sx), y0f = floorf(sy);
        int x0 = (int)x0f, y0 = (int)y0f;
        float fx = sx - x0f, fy = sy - y0f;
        const float* xr = s_xg + c * 64;
        float acc = 0.f;
        if (y0 >= 0 && y0 < 8) {
            if (x0 >= 0 && x0 < 8)         acc = fmaf(xr[y0 * 8 + x0],       (1.f - fx) * (1.f - fy), acc);
            if (x0 + 1 >= 0 && x0 + 1 < 8) acc = fmaf(xr[y0 * 8 + x0 + 1],   fx * (1.f - fy),         acc);
        }
        if (y0 + 1 >= 0 && y0 + 1 < 8) {
            if (x0 >= 0 && x0 < 8)         acc = fmaf(xr[(y0 + 1) * 8 + x0],     (1.f - fx) * fy, acc);
            if (x0 + 1 >= 0 && x0 + 1 < 8) acc = fmaf(xr[(y0 + 1) * 8 + x0 + 1], fx * fy,         acc);
        }
        s_kv[c * 4 + j] = acc;
    }
    __syncthreads();

    // ---- P5: k, v projections ----
    {
        int o = tid >> 2, j = tid & 3;
        float ak = 0.f, av = 0.f;
        const float* wkr = s_w + o * 32;
        const float* wvr = s_w + 2048 + o * 32;
        #pragma unroll 8
        for (int c = 0; c < 32; c++) {
            float kvv = s_kv[c * 4 + j];
            ak = fmaf(wkr[c], kvv, ak);
            av = fmaf(wvr[c], kvv, av);
        }
        s_kk[o * 4 + j] = ak;
        s_vv[o * 4 + j] = av;
    }
    __syncthreads();

    // ---- P6a: sim -> s_lg ; compute h1 in registers ----
    float2 h1[32];
    {
        int i = tid >> 2, j = tid & 3;
        float s0 = 0.f, s1 = 0.f, s2 = 0.f, s3 = 0.f;
        #pragma unroll
        for (int o = 0; o < 64; o += 4) {
            s0 = fmaf(s_q[(o + 0) * 65 + i], s_kk[(o + 0) * 4 + j], s0);
            s1 = fmaf(s_q[(o + 1) * 65 + i], s_kk[(o + 1) * 4 + j], s1);
            s2 = fmaf(s_q[(o + 2) * 65 + i], s_kk[(o + 2) * 4 + j], s2);
            s3 = fmaf(s_q[(o + 3) * 65 + i], s_kk[(o + 3) * 4 + j], s3);
        }
        s_lg[tid] = ((s0 + s1) + (s2 + s3)) * 0.125f;

        float qpx = (float)(i & 7) * (2.f / 7.f) - 1.f;
        float qpy = (float)(i >> 3) * (2.f / 7.f) - 1.f;
        float px = qpx - s_sp[8 + j];
        float py = qpy - s_sp[12 + j];
        float bx = copysignf(log1pf(fabsf(px)), px);
        float by = copysignf(log1pf(fabsf(py)), py);

        #pragma unroll
        for (int k2 = 0; k2 < 32; k2++) {
            float a0 = fmaf(bx, s_c1[2 * k2],     fmaf(by, s_c1[64 + 2 * k2],     s_b1[2 * k2]));
            float a1 = fmaf(bx, s_c1[2 * k2 + 1], fmaf(by, s_c1[64 + 2 * k2 + 1], s_b1[2 * k2 + 1]));
            h1[k2].x = fmaxf(a0, 0.f);
            h1[k2].y = fmaxf(a1, 0.f);
        }
    }
    __syncthreads();   // all reads of s_q/s_kk done; overlay region now free

    // ---- P6b: store h1 as bf16 [p][68] over [0,10304) ----
    {
        char* base = (char*)sm + tid * 136;   // 68 bf16 * 2B
        #pragma unroll
        for (int k2 = 0; k2 < 32; k2++) {
            __nv_bfloat162 pr = __float22bfloat162_rn(make_float2(h1[k2].x, h1[k2].y));
            *(__nv_bfloat162*)(base + 4 * k2) = pr;
        }
    }
    __syncthreads();

    // ---- P7: CPB layer2 as 256x64x64 bf16 MMA + epilogue ----
    {
        int wid = tid >> 5, lane = tid & 31;
        int p0 = wid * 32;
        const char* h1b = (const char*)sm;
        const char* w2b = (const char*)(sm + SM_W2B);

        float d[2][8][4];
        #pragma unroll
        for (int t = 0; t < 2; t++)
            #pragma unroll
            for (int nt = 0; nt < 8; nt++)
                #pragma unroll
                for (int r = 0; r < 4; r++) d[t][nt][r] = 0.f;

        #pragma unroll
        for (int ks = 0; ks < 4; ks++) {
            int k0 = ks * 16;
            int cb = (k0 + 2 * (lane & 3)) * 2;
            unsigned a[2][4];
            #pragma unroll
            for (int t = 0; t < 2; t++) {
                int row = p0 + t * 16 + (lane >> 2);
                a[t][0] = *(const unsigned*)(h1b + row * 136 + cb);
                a[t][1] = *(const unsigned*)(h1b + (row + 8) * 136 + cb);
                a[t][2] = *(const unsigned*)(h1b + row * 136 + cb + 16);
                a[t][3] = *(const unsigned*)(h1b + (row + 8) * 136 + cb + 16);
            }
            #pragma unroll
            for (int nt = 0; nt < 8; nt++) {
                int oo = nt * 8 + (lane >> 2);
                unsigned b0 = *(const unsigned*)(w2b + oo * 144 + cb);
                unsigned b1 = *(const unsigned*)(w2b + oo * 144 + cb + 16);
                mma_bf16(d[0][nt], a[0], b0, b1);
                mma_bf16(d[1][nt], a[1], b0, b1);
            }
        }
        // epilogue: h2 = D + b2; relu; dot c3; add to logits
        float b2v[16], c3v[16];
        #pragma unroll
        for (int nt = 0; nt < 8; nt++) {
            int o0 = nt * 8 + 2 * (lane & 3);
            b2v[2 * nt]     = s_b2[o0];     b2v[2 * nt + 1] = s_b2[o0 + 1];
            c3v[2 * nt]     = s_c3[o0];     c3v[2 * nt + 1] = s_c3[o0 + 1];
        }
        float bias3 = s_b3[0];
        #pragma unroll
        for (int t = 0; t < 2; t++)
            #pragma unroll
            for (int hf = 0; hf < 2; hf++) {
                float part = 0.f;
                #pragma unroll
                for (int nt = 0; nt < 8; nt++) {
                    float h2a = d[t][nt][hf * 2 + 0] + b2v[2 * nt];
                    float h2b = d[t][nt][hf * 2 + 1] + b2v[2 * nt + 1];
                    part = fmaf(c3v[2 * nt],     fmaxf(h2a, 0.f), part);
                    part = fmaf(c3v[2 * nt + 1], fmaxf(h2b, 0.f), part);
                }
                part += __shfl_xor_sync(0xffffffffu, part, 1);
                part += __shfl_xor_sync(0xffffffffu, part, 2);
                if ((lane & 3) == 0) {
                    int p = p0 + t * 16 + hf * 8 + (lane >> 2);
                    s_lg[p] += part + bias3;
                }
            }
    }
    __syncthreads();

    // ---- P8: softmax over the 4 keys ----
    if (tid < 64) {
        float l0 = s_lg[tid * 4], l1 = s_lg[tid * 4 + 1], l2 = s_lg[tid * 4 + 2], l3 = s_lg[tid * 4 + 3];
        float m = fmaxf(fmaxf(l0, l1), fmaxf(l2, l3));
        float e0 = expf(l0 - m), e1 = expf(l1 - m), e2 = expf(l2 - m), e3 = expf(l3 - m);
        float inv = 1.f / (e0 + e1 + e2 + e3);
        s_at[tid * 4]     = e0 * inv;
        s_at[tid * 4 + 1] = e1 * inv;
        s_at[tid * 4 + 2] = e2 * inv;
        s_at[tid * 4 + 3] = e3 * inv;
    }
    __syncthreads();

    // ---- P9: out[i][d] = sum_j attn[i][j] v[d][j] -> g_ao [n][i][r] (transposed!) ----
    {
        int i = tid >> 2, dg = tid & 3, d0 = dg * 16;
        float a0 = s_at[i * 4 + 0], a1 = s_at[i * 4 + 1];
        float a2 = s_at[i * 4 + 2], a3 = s_at[i * 4 + 3];
        float* dst = g_ao + ((long)n * 64 + i) * 512 + g * 64 + d0;
        #pragma unroll
        for (int q4 = 0; q4 < 4; q4++) {
            int dd = d0 + q4 * 4;
            float4 o;
            o.x = a0 * s_vv[(dd + 0) * 4 + 0] + a1 * s_vv[(dd + 0) * 4 + 1]
                + a2 * s_vv[(dd + 0) * 4 + 2] + a3 * s_vv[(dd + 0) * 4 + 3];
            o.y = a0 * s_vv[(dd + 1) * 4 + 0] + a1 * s_vv[(dd + 1) * 4 + 1]
                + a2 * s_vv[(dd + 1) * 4 + 2] + a3 * s_vv[(dd + 1) * 4 + 3];
            o.z = a0 * s_vv[(dd + 2) * 4 + 0] + a1 * s_vv[(dd + 2) * 4 + 1]
                + a2 * s_vv[(dd + 2) * 4 + 2] + a3 * s_vv[(dd + 2) * 4 + 3];
            o.w = a0 * s_vv[(dd + 3) * 4 + 0] + a1 * s_vv[(dd + 3) * 4 + 1]
                + a2 * s_vv[(dd + 3) * 4 + 2] + a3 * s_vv[(dd + 3) * 4 + 3];
            *(float4*)(dst + q4 * 4) = o;
        }
    }
}

// ---------------- K3: output projection 512->256 via tf32 MMA ----------------
// per CTA: D[256c x 64i] = sum_r wo[c][r] * att[r][i], K staged in 16 slabs of 32
#define K3_SMEM_BYTES ((256 * 36 + 64 * 36) * 4)
__global__ void __launch_bounds__(256) k3_outproj(const float* __restrict__ wo,
                                                  const float* __restrict__ bo,
                                                  float* __restrict__ out) {
    extern __shared__ float sm3[];
    float* s_wb = sm3;             // [256][36]
    float* s_ab = sm3 + 256 * 36;  // [64][36]
    int n = blockIdx.x, tid = threadIdx.x;
    int wid = tid >> 5, lane = tid & 31;

    float d[2][8][4];
    #pragma unroll
    for (int t = 0; t < 2; t++)
        #pragma unroll
        for (int nt = 0; nt < 8; nt++)
            #pragma unroll
            for (int r = 0; r < 4; r++) d[t][nt][r] = 0.f;

    const float4* wsrc = (const float4*)wo;
    const float4* asrc = (const float4*)(g_ao + (long)n * 64 * 512);

    for (int sb = 0; sb < 16; sb++) {
        int k4 = sb * 8;   // k0/4
        __syncthreads();
        for (int idx = tid; idx < 2048; idx += 256) {
            int c = idx >> 3, f = idx & 7;
            float4 v = __ldg(wsrc + c * 128 + k4 + f);
            float* dst = s_wb + c * 36 + f * 4;
            dst[0] = cvt_tf32(v.x); dst[1] = cvt_tf32(v.y);
            dst[2] = cvt_tf32(v.z); dst[3] = cvt_tf32(v.w);
        }
        for (int idx = tid; idx < 512; idx += 256) {
            int i = idx >> 3, f = idx & 7;
            float4 v = asrc[i * 128 + k4 + f];
            float* dst = s_ab + i * 36 + f * 4;
            dst[0] = cvt_tf32(v.x); dst[1] = cvt_tf32(v.y);
            dst[2] = cvt_tf32(v.z); dst[3] = cvt_tf32(v.w);
        }
        __syncthreads();
        #pragma unroll
        for (int ks = 0; ks < 4; ks++) {
            int kk = ks * 8 + (lane & 3);
            unsigned a[2][4];
            #pragma unroll
            for (int t = 0; t < 2; t++) {
                int row = wid * 32 + t * 16 + (lane >> 2);
                a[t][0] = __float_as_uint(s_wb[row * 36 + kk]);
                a[t][1] = __float_as_uint(s_wb[(row + 8) * 36 + kk]);
                a[t][2] = __float_as_uint(s_wb[row * 36 + kk + 4]);
                a[t][3] = __float_as_uint(s_wb[(row + 8) * 36 + kk + 4]);
            }
            #pragma unroll
            for (int nt = 0; nt < 8; nt++) {
                int col = nt * 8 + (lane >> 2);
                unsigned b0 = __float_as_uint(s_ab[col * 36 + kk]);
                unsigned b1 = __float_as_uint(s_ab[col * 36 + kk + 4]);
                mma_tf32(d[0][nt], a[0], b0, b1);
                mma_tf32(d[1][nt], a[1], b0, b1);
            }
        }
    }

    // epilogue: add bias, un-patchify, store
    int it = n >> 7, jt = (n >> 4) & 7, b = n & 15;
    #pragma unroll
    for (int t = 0; t < 2; t++)
        #pragma unroll
        for (int hf = 0; hf < 2; hf++) {
            int c = wid * 32 + t * 16 + hf * 8 + (lane >> 2);
            float bias = __ldg(bo + c);
            #pragma unroll
            for (int nt = 0; nt < 8; nt++) {
                int i = nt * 8 + 2 * (lane & 3);
                int hh = it * 8 + (i >> 3), ww = jt * 8 + (i & 7);
                float2 v;
                v.x = d[t][nt][hf * 2 + 0] + bias;
                v.y = d[t][nt][hf * 2 + 1] + bias;
                *(float2*)(out + (((long)b * 256 + c) * 64 + hh) * 64 + ww) = v;
            }
        }
}

// ---------------- launcher ----------------
extern "C" void kernel_launch(void* const* d_in, const int* in_sizes, int n_in,
                              void* d_out, int out_size) {
    (void)in_sizes; (void)n_in; (void)out_size;
    const float* x   = (const float*)d_in[0];
    const float* lng = (const float*)d_in[1];
    const float* lnb = (const float*)d_in[2];
    const float* wq  = (const float*)d_in[3];
    const float* wk  = (const float*)d_in[4];
    const float* wv  = (const float*)d_in[5];
    const float* ow1 = (const float*)d_in[6];
    const float* ob1 = (const float*)d_in[7];
    const float* ow2 = (const float*)d_in[8];
    const float* cw1 = (const float*)d_in[9];
    const float* cb1 = (const float*)d_in[10];
    const float* cw2 = (const float*)d_in[11];
    const float* cb2 = (const float*)d_in[12];
    const float* cw3 = (const float*)d_in[13];
    const float* cb3 = (const float*)d_in[14];
    const float* wo  = (const float*)d_in[15];
    const float* bo  = (const float*)d_in[16];
    float* out = (float*)d_out;

    k1_ln_patch<<<2048, 256>>>(x, lng, lnb);
    cudaFuncSetAttribute(k2_attn, cudaFuncAttributeMaxDynamicSharedMemorySize, K2_SMEM_BYTES);
    k2_attn<<<NG, 256, K2_SMEM_BYTES>>>(wq, wk, wv, ow1, ob1, ow2,
                                        cw1, cb1, cw2, cb2, cw3, cb3);
    cudaFuncSetAttribute(k3_outproj, cudaFuncAttributeMaxDynamicSharedMemorySize, K3_SMEM_BYTES);
    k3_outproj<<<NPATCH, 256, K3_SMEM_BYTES>>>(wo, bo, out);
}